// round 14
// baseline (speedup 1.0000x reference)
#include <cuda_runtime.h>
#include <stdint.h>
#include <math.h>

// ---------------------------------------------------------------------------
// GNNLoss fused single-kernel (R14 = R13 + missing <stdint.h>).
//
// Theory: R3-R12 showed the edge loop is scoreboard-latency-bound (~45
// issueable instrs/warp-iter vs ~600cyc LDG chain; register lookahead can't
// cover it -- every attempt hit the reg ceiling / spilled). Stage the three
// edge streams into smem with cp.async (LDGSTS): in-flight bytes become
// stage capacity (2 x 12KB/SM), warps block only on cp.async.wait_group,
// registers stay ~35.
//
// Proven parts kept: 1024thr x 1 CTA/SM, 200KB u8 hash filter in smem,
// focal(t=0) unconditional hot path (P(t=1)~6e-5), corrections behind two
// warp votes, exact u16 key fallback, grid barrier, per-block partials.
//
// key[node]  = (pi==0) ? 0 : (batch<<10)|pi     (u16 exact)
// hash[node] = (key==0) ? 0 : (key % 255) + 1   (u8 filter, smem)
// ---------------------------------------------------------------------------

#define MAX_NODES   262144
#define MAX_BLOCKS  512
#define NTHREADS    1024
#define STAGE_BYTES 12288   // 3 arrays x 4KB (1024 x 4B)

__device__ __align__(16) unsigned short g_keys[MAX_NODES];
__device__ __align__(16) unsigned char  g_hash[MAX_NODES];
__device__ float g_part_es[MAX_BLOCKS];
__device__ int   g_part_ec[MAX_BLOCKS];
__device__ float g_part_ns[MAX_BLOCKS];
__device__ int   g_part_nc[MAX_BLOCKS];
__device__ unsigned int g_bar0;   // zero-init; reset by block 0 each run
__device__ unsigned int g_bar1;

__device__ __forceinline__ unsigned int smem_u32(const void* p) {
    unsigned int a;
    asm("{ .reg .u64 t; cvta.to.shared.u64 t, %1; cvt.u32.u64 %0, t; }"
        : "=r"(a) : "l"(p));
    return a;
}

__device__ __forceinline__ void cp_async4(unsigned int saddr, const void* gptr) {
    asm volatile("cp.async.ca.shared.global [%0], [%1], 4;"
                 :: "r"(saddr), "l"(gptr));
}
#define CP_COMMIT() asm volatile("cp.async.commit_group;" ::: "memory")
#define CP_WAIT1()  asm volatile("cp.async.wait_group 1;" ::: "memory")

__device__ __forceinline__ float rcp_approx(float x) {
    float y;
    asm("rcp.approx.f32 %0, %1;" : "=f"(y) : "f"(x));
    return y;
}

// generic focal term (node phase / tail only)
__device__ __forceinline__ float focal_term(float x, bool t) {
    float a  = fabsf(x);
    float em = __expf(-a);
    float w  = 1.0f + em;
    float L  = __logf(w);
    float q  = em * rcp_approx(w);
    bool  m  = ((x >= 0.0f) == t);
    float omp = m ? q : (1.0f - q);
    float ce  = m ? L : (a + L);
    float at  = t ? 0.25f : 0.75f;
    return at * ce * omp * omp;
}

// hot-path focal with t = 0 hard-coded
__device__ __forceinline__ float focal_t0(float x) {
    float a  = fabsf(x);
    float em = __expf(-a);
    float w  = 1.0f + em;
    float L  = __logf(w);
    float q  = em * rcp_approx(w);
    bool  neg = (x < 0.0f);
    float omp = neg ? q : (1.0f - q);
    float ce  = neg ? L : (a + L);
    return 0.75f * ce * omp * omp;
}

// rare correction: loss(x,1) - loss(x,0)
__device__ __forceinline__ float focal_delta(float x) {
    float a  = fabsf(x);
    float em = __expf(-a);
    float w  = 1.0f + em;
    float L  = __logf(w);
    float q  = em * rcp_approx(w);
    bool  pos = (x >= 0.0f);
    float omp1 = pos ? q : (1.0f - q);
    float ce1  = pos ? L : (a + L);
    float omp0 = pos ? (1.0f - q) : q;
    float ce0  = pos ? (a + L) : L;
    return 0.25f * ce1 * omp1 * omp1 - 0.75f * ce0 * omp0 * omp0;
}

__device__ __forceinline__ void block_reduce_store(float s, int c,
                                                   float* ps, int* pc) {
    #pragma unroll
    for (int o = 16; o > 0; o >>= 1) {
        s += __shfl_down_sync(0xFFFFFFFFu, s, o);
        c += __shfl_down_sync(0xFFFFFFFFu, c, o);
    }
    __shared__ float sh_s[32];
    __shared__ int   sh_c[32];
    int lane = threadIdx.x & 31;
    int wid  = threadIdx.x >> 5;
    if (lane == 0) { sh_s[wid] = s; sh_c[wid] = c; }
    __syncthreads();
    int nw = (blockDim.x + 31) >> 5;
    if (wid == 0) {
        s = (lane < nw) ? sh_s[lane] : 0.0f;
        c = (lane < nw) ? sh_c[lane] : 0;
        #pragma unroll
        for (int o = 16; o > 0; o >>= 1) {
            s += __shfl_down_sync(0xFFFFFFFFu, s, o);
            c += __shfl_down_sync(0xFFFFFFFFu, c, o);
        }
        if (lane == 0) { ps[blockIdx.x] = s; pc[blockIdx.x] = c; }
    }
    __syncthreads();
}

__device__ __forceinline__ void grid_barrier(unsigned int* bar, int nb) {
    __syncthreads();
    if (threadIdx.x == 0) {
        __threadfence();
        atomicAdd(bar, 1u);
        while (*(volatile unsigned int*)bar < (unsigned int)nb) { }
    }
    __syncthreads();
    __threadfence();
}

__global__ void __launch_bounds__(NTHREADS, 1)
fused_kernel(const float* __restrict__ edge_logits,
             const float* __restrict__ node_logits,
             const int*   __restrict__ batch,
             const int*   __restrict__ pinst,
             const int*   __restrict__ src,
             const int*   __restrict__ dst,
             int E, int N, int tbl_bytes,
             float* __restrict__ out) {
    extern __shared__ unsigned char sh[];
    int tid     = threadIdx.x;
    int nb      = gridDim.x;
    int gtid    = blockIdx.x * blockDim.x + tid;
    int gstride = nb * blockDim.x;

    // ---- phase 1: nodes (build key + hash tables, node loss/acc) ----
    float ns = 0.0f; int nc = 0;
    for (int i = gtid; i < N; i += gstride) {
        int p = pinst[i];
        int b = batch[i];
        unsigned short key = (p == 0) ? (unsigned short)0
                                      : (unsigned short)((b << 10) | p);
        g_keys[i] = key;
        g_hash[i] = (key == 0) ? (unsigned char)0
                               : (unsigned char)((key % 255) + 1);
        float x = node_logits[i];
        bool  t = (p != 0);
        ns += focal_term(x, t);
        nc += ((x > 0.0f) == t) ? 1 : 0;
    }
    block_reduce_store(ns, nc, g_part_ns, g_part_nc);

    grid_barrier(&g_bar0, nb);   // tables complete, visible in L2

    // ---- broadcast hash table into shared memory ----
    int nw4 = (N + 15) >> 4;
    const uint4* hv = (const uint4*)g_hash;
    uint4* s4 = (uint4*)sh;
    for (int i = tid; i < nw4; i += NTHREADS) s4[i] = hv[i];
    __syncthreads();

    // ---- phase 2: edges via cp.async double-buffered staging ----
    // 1024-edge blocks; thread t owns edge (block<<10)+t; 12B staged each.
    float es = 0.0f; int ec = 0;
    int nfull = E >> 10;
    unsigned int sbase = smem_u32(sh) + (unsigned int)tbl_bytes;
    unsigned int toff  = 4u * (unsigned int)tid;

    // prologue: issue 2 stages (always commit to keep group counts uniform)
    #pragma unroll
    for (int p = 0; p < 2; p++) {
        int bb = blockIdx.x + p * nb;
        if (bb < nfull) {
            size_t base = ((size_t)bb << 10) + tid;
            unsigned int st = sbase + p * STAGE_BYTES + toff;
            cp_async4(st,        edge_logits + base);
            cp_async4(st + 4096, src + base);
            cp_async4(st + 8192, dst + base);
        }
        CP_COMMIT();
    }

    int k = 0;
    for (int bb = blockIdx.x; bb < nfull; bb += nb, k++) {
        CP_WAIT1();                         // stage k ready
        int soff = tbl_bytes + (k & 1) * STAGE_BYTES + (tid << 2);
        float x  = *(const float*)(sh + soff);
        int   si = *(const int*)  (sh + soff + 4096);
        int   di = *(const int*)  (sh + soff + 8192);

        // hash filter (smem gathers) + unconditional t=0 loss/acc
        unsigned int hs = sh[si];
        unsigned int hd = sh[di];
        bool n = (hs == hd) & (hs != 0u);
        es += focal_t0(x);
        ec += (x <= 0.0f) ? 1 : 0;

        // rare corrections behind two warp votes (~13% / ~0.2% of warp-iters)
        if (__any_sync(0xFFFFFFFFu, n)) {
            bool t = n && (__ldg(&g_keys[si]) == __ldg(&g_keys[di]));
            if (__any_sync(0xFFFFFFFFu, t)) {
                if (t) { es += focal_delta(x); ec += (x > 0.0f) ? 1 : -1; }
            }
        }

        // refill the stage just consumed (safe: all its values already
        // consumed by instructions issued above in program order)
        int bn = bb + 2 * nb;
        if (bn < nfull) {
            size_t base = ((size_t)bn << 10) + tid;
            unsigned int st = sbase + (k & 1) * STAGE_BYTES + toff;
            cp_async4(st,        edge_logits + base);
            cp_async4(st + 4096, src + base);
            cp_async4(st + 8192, dst + base);
        }
        CP_COMMIT();
    }
    asm volatile("cp.async.wait_group 0;" ::: "memory");

    // tail edges (E % 1024)
    if (blockIdx.x == 0 && tid == 0) {
        for (int e = nfull << 10; e < E; e++) {
            int sidx = src[e], didx = dst[e];
            unsigned short ks = g_keys[sidx], kd = g_keys[didx];
            bool t = (ks == kd) && (ks != 0);
            float xe = edge_logits[e];
            es += focal_term(xe, t);
            ec += ((xe > 0.0f) == t) ? 1 : 0;
        }
    }
    block_reduce_store(es, ec, g_part_es, g_part_ec);

    // ---- final barrier; block 0 reduces partials and writes outputs ----
    if (tid == 0) { __threadfence(); atomicAdd(&g_bar1, 1u); }
    if (blockIdx.x != 0) return;
    if (tid == 0) {
        while (*(volatile unsigned int*)&g_bar1 < (unsigned int)nb) { }
    }
    __syncthreads();
    __threadfence();

    if (tid < 32) {
        double des = 0.0, dns = 0.0;
        int iec = 0, inc = 0;
        for (int q = tid; q < nb; q += 32) {
            des += (double)g_part_es[q];
            dns += (double)g_part_ns[q];
            iec += g_part_ec[q];
            inc += g_part_nc[q];
        }
        #pragma unroll
        for (int o = 16; o > 0; o >>= 1) {
            des += __shfl_down_sync(0xFFFFFFFFu, des, o);
            dns += __shfl_down_sync(0xFFFFFFFFu, dns, o);
            iec += __shfl_down_sync(0xFFFFFFFFu, iec, o);
            inc += __shfl_down_sync(0xFFFFFFFFu, inc, o);
        }
        if (tid == 0) {
            float edge_loss = (float)(des / (double)E);
            float node_loss = (float)(dns / (double)N);
            out[0] = edge_loss + node_loss;  // EDGE_W = NODE_W = 1
            out[1] = edge_loss;
            out[2] = node_loss;
            out[3] = (float)((double)iec / (double)E);
            out[4] = (float)((double)inc / (double)N);
            g_bar0 = 0;                      // reset for next graph replay
            g_bar1 = 0;
        }
    }
}

extern "C" void kernel_launch(void* const* d_in, const int* in_sizes, int n_in,
                              void* d_out, int out_size) {
    const float* edge_logits = (const float*)d_in[0];
    const float* node_logits = (const float*)d_in[1];
    const int*   batch       = (const int*)d_in[2];
    const int*   pinst       = (const int*)d_in[3];
    const int*   edge_index  = (const int*)d_in[4];

    int E = in_sizes[0];
    int N = in_sizes[1];
    const int* src = edge_index;
    const int* dst = edge_index + E;
    float* out = (float*)d_out;

    int tbl_bytes  = ((N + 15) >> 4) << 4;          // u8 hash table (200KB)
    int smem_bytes = tbl_bytes + 2 * STAGE_BYTES;   // + 24KB staging
    cudaFuncSetAttribute(fused_kernel,
                         cudaFuncAttributeMaxDynamicSharedMemorySize,
                         smem_bytes);

    int sm_count = 148;
    cudaDeviceGetAttribute(&sm_count, cudaDevAttrMultiProcessorCount, 0);

    // size the grid by ACTUAL occupancy so the grid barrier cannot deadlock
    int per_sm = 1;
    cudaOccupancyMaxActiveBlocksPerMultiprocessor(&per_sm, fused_kernel,
                                                  NTHREADS, smem_bytes);
    if (per_sm < 1) per_sm = 1;
    int nblocks = sm_count * per_sm;
    if (nblocks > MAX_BLOCKS) nblocks = MAX_BLOCKS;

    fused_kernel<<<nblocks, NTHREADS, smem_bytes>>>(edge_logits, node_logits,
                                                    batch, pinst, src, dst,
                                                    E, N, tbl_bytes, out);
}